// round 14
// baseline (speedup 1.0000x reference)
#include <cuda_runtime.h>
#include <cuda_bf16.h>
#include <cstdint>

#define EDIM 100
#define NDIM 50
#define TDIM 8
#define CDIM 4
#define UDIM 100
#define LDIM 1000
#define NPAIR 4950
#define KPAD  5120
#define NP    128
#define KSPLIT 2
#define KSLICE (KPAD / KSPLIT)        // 2560
#define NKSTEP (KPAD / 16)            // 320
#define NKS_SL (KSLICE / 16)          // 160
#define NCHUNK (NKS_SL / 4)           // 40
#define MAXB  8192
#define TMC   64
#define KF    208
#define NKSF  13
#define NLT   125
#define KH    208
#define NKH   13
#define NTH   13

// ---------------- device scratch ----------------
__device__ __align__(16) int2  g_pairs[KPAD];
__device__ float g_q[MAXB * 2 * EDIM];
__device__ float g_h5[MAXB * EDIM];
__device__ float g_h7p[KSPLIT * MAXB * NP];
__device__ __align__(16) float g_u[2 * EDIM];
__device__ float g_z0[2];
__device__ float g_S[EDIM * EDIM];        // W8a @ W6
__device__ float g_w[UDIM];               // folded bias vector
__device__ float g_P1[EDIM * LDIM];
__device__ float g_Q1b[EDIM * LDIM];
__device__ float g_c[LDIM];
__device__ __align__(16) uint2 g_Bfh[NKSTEP * 16 * 32];
__device__ __align__(16) uint2 g_Bfl[NKSTEP * 16 * 32];
__device__ __align__(16) uint2 g_Pfh[NKSF * NLT * 32];
__device__ __align__(16) uint2 g_Pfl[NKSF * NLT * 32];
__device__ __align__(16) uint2 g_W5fh[NKH * NTH * 32];
__device__ __align__(16) uint2 g_W5fl[NKH * NTH * 32];

// ---------------- helpers ----------------
__device__ __forceinline__ void mma16816(float* d, const uint32_t* a, uint2 b) {
    asm volatile(
        "mma.sync.aligned.m16n8k16.row.col.f32.bf16.bf16.f32 "
        "{%0,%1,%2,%3}, {%4,%5,%6,%7}, {%8,%9}, {%0,%1,%2,%3};"
        : "+f"(d[0]), "+f"(d[1]), "+f"(d[2]), "+f"(d[3])
        : "r"(a[0]), "r"(a[1]), "r"(a[2]), "r"(a[3]), "r"(b.x), "r"(b.y));
}
__device__ __forceinline__ void mkfrag(const float* rw, int2 p0, int2 p1,
                                       uint32_t& hi, uint32_t& lo) {
    float v0 = rw[p0.x] * rw[p0.y];
    float v1 = rw[p1.x] * rw[p1.y];
    __nv_bfloat16 h0 = __float2bfloat16(v0), h1 = __float2bfloat16(v1);
    __nv_bfloat16 l0 = __float2bfloat16(v0 - __bfloat162float(h0));
    __nv_bfloat16 l1 = __float2bfloat16(v1 - __bfloat162float(h1));
    hi = (uint32_t)__bfloat16_as_ushort(h0) | ((uint32_t)__bfloat16_as_ushort(h1) << 16);
    lo = (uint32_t)__bfloat16_as_ushort(l0) | ((uint32_t)__bfloat16_as_ushort(l1) << 16);
}
__device__ __forceinline__ void splitpack(float v0, float v1,
                                          uint32_t& hi, uint32_t& lo) {
    __nv_bfloat16 h0 = __float2bfloat16(v0), h1 = __float2bfloat16(v1);
    __nv_bfloat16 l0 = __float2bfloat16(v0 - __bfloat162float(h0));
    __nv_bfloat16 l1 = __float2bfloat16(v1 - __bfloat162float(h1));
    hi = (uint32_t)__bfloat16_as_ushort(h0) | ((uint32_t)__bfloat16_as_ushort(h1) << 16);
    lo = (uint32_t)__bfloat16_as_ushort(l0) | ((uint32_t)__bfloat16_as_ushort(l1) << 16);
}

// ---------------- pair table (int-only) ----------------
__global__ void k_pairs() {
    int p = blockIdx.x * blockDim.x + threadIdx.x;
    if (p >= KPAD) return;
    int i = 0, j = 0;
    if (p < NPAIR) {
        int rem = p;
        while (rem >= EDIM - 1 - i) { rem -= EDIM - 1 - i; i++; }
        j = i + 1 + rem;
    }
    g_pairs[p] = make_int2(i, j);
}

// ---------------- prep1: S/w/u/z0 folds FIRST, then bfrag, then w5f --------
// Latency-bound small segments go first so their blocks overlap the wide
// bfrag segment instead of running as a lone 41-block kernel.
#define P1_S  (EDIM * EDIM)                     // S: 10000
#define P1_W  (P1_S + UDIM)                     // w
#define P1_U  (P1_W + 2 * EDIM)                 // u
#define P1_Z  (P1_U + 2)                        // z0
#define P1_BF (P1_Z + NKSTEP * 512)             // W7 fragments
#define P1_W5 (P1_BF + NKH * NTH * 32)          // W5 fragments

__global__ void k_prep1(const float* __restrict__ v, const float* __restrict__ W7,
                        const float* __restrict__ W5,
                        const float* __restrict__ W1, const float* __restrict__ b1,
                        const float* __restrict__ W2,
                        const float* __restrict__ W3, const float* __restrict__ b3,
                        const float* __restrict__ W4,
                        const float* __restrict__ W6, const float* __restrict__ W8,
                        const float* __restrict__ b6, const float* __restrict__ b7,
                        const float* __restrict__ b8) {
    int idx = blockIdx.x * blockDim.x + threadIdx.x;
    if (idx < P1_S) {
        int u = idx / EDIM, e = idx % EDIM;
        float a0 = 0.f, a1 = 0.f, a2 = 0.f, a3 = 0.f;
        #pragma unroll 4
        for (int k = 0; k < EDIM; k += 4) {
            a0 += W8[u * 2 * EDIM + k] * W6[k * EDIM + e];
            a1 += W8[u * 2 * EDIM + k + 1] * W6[(k + 1) * EDIM + e];
            a2 += W8[u * 2 * EDIM + k + 2] * W6[(k + 2) * EDIM + e];
            a3 += W8[u * 2 * EDIM + k + 3] * W6[(k + 3) * EDIM + e];
        }
        g_S[idx] = (a0 + a1) + (a2 + a3);
    } else if (idx < P1_W) {
        int u = idx - P1_S;
        float a = b8[u];
        #pragma unroll 4
        for (int k = 0; k < EDIM; k++) {
            a += b6[k] * W8[u * 2 * EDIM + k];
            a += b7[k] * W8[u * 2 * EDIM + EDIM + k];
        }
        g_w[u] = a;
    } else if (idx < P1_U) {
        int j = idx - P1_W;
        int pool = j / EDIM, e = j % EDIM;
        const float* Wa = pool ? W3 : W1;
        const float* Wb = pool ? W4 : W2;
        float u = 0.f;
        #pragma unroll
        for (int t = 0; t < TDIM; t++) u += Wb[t] * Wa[t * EDIM + e];
        g_u[j] = u;
    } else if (idx < P1_Z) {
        int pool = idx - P1_U;
        const float* ba = pool ? b3 : b1;
        const float* Wb = pool ? W4 : W2;
        float z = 0.f;
        #pragma unroll
        for (int t = 0; t < TDIM; t++) z += Wb[t] * ba[t];
        g_z0[pool] = z;
    } else if (idx < P1_BF) {
        int fi = idx - P1_Z;
        int ks = fi >> 9, rem = fi & 511;
        int nt = rem >> 5, l = rem & 31;
        int n = nt * 8 + (l >> 2);
        int c0 = (l & 3) * 2;
        uint32_t hreg[2], lreg[2];
        #pragma unroll
        for (int r = 0; r < 2; r++) {
            uint32_t hp = 0, lp = 0;
            #pragma unroll
            for (int h = 0; h < 2; h++) {
                int k = ks * 16 + r * 8 + c0 + h;
                float w = 0.f;
                if (k < NPAIR && n < EDIM) {
                    int2 ij = g_pairs[k];
                    float vv = 0.f;
                    #pragma unroll
                    for (int cc = 0; cc < CDIM; cc++)
                        vv += v[ij.x * CDIM + cc] * v[ij.y * CDIM + cc];
                    w = W7[n * NPAIR + k] * vv;
                }
                __nv_bfloat16 hi = __float2bfloat16(w);
                __nv_bfloat16 lo = __float2bfloat16(w - __bfloat162float(hi));
                hp |= (uint32_t)__bfloat16_as_ushort(hi) << (h * 16);
                lp |= (uint32_t)__bfloat16_as_ushort(lo) << (h * 16);
            }
            hreg[r] = hp; lreg[r] = lp;
        }
        g_Bfh[fi] = make_uint2(hreg[0], hreg[1]);
        g_Bfl[fi] = make_uint2(lreg[0], lreg[1]);
    } else if (idx < P1_W5) {
        int fi = idx - P1_BF;
        int ks = fi / (NTH * 32), rem = fi % (NTH * 32);
        int nt = rem >> 5, l = rem & 31;
        int n = nt * 8 + (l >> 2);
        int c0 = (l & 3) * 2;
        uint32_t hreg[2], lreg[2];
        #pragma unroll
        for (int r = 0; r < 2; r++) {
            uint32_t hp = 0, lp = 0;
            #pragma unroll
            for (int h = 0; h < 2; h++) {
                int k = ks * 16 + r * 8 + c0 + h;
                float w = (k < 2 * EDIM && n < EDIM) ? W5[n * 2 * EDIM + k] : 0.f;
                __nv_bfloat16 hi = __float2bfloat16(w);
                __nv_bfloat16 lo = __float2bfloat16(w - __bfloat162float(hi));
                hp |= (uint32_t)__bfloat16_as_ushort(hi) << (h * 16);
                lp |= (uint32_t)__bfloat16_as_ushort(lo) << (h * 16);
            }
            hreg[r] = hp; lreg[r] = lp;
        }
        g_W5fh[fi] = make_uint2(hreg[0], hreg[1]);
        g_W5fl[fi] = make_uint2(lreg[0], lreg[1]);
    }
}

// ---------------- prepB: one pass over LE -> P1, Q1b, c (4-way ILP) --------
__global__ void k_prepB(const float* __restrict__ W8, const float* __restrict__ LE) {
    int idx = blockIdx.x * blockDim.x + threadIdx.x;
    if (idx >= (2 * EDIM + 1) * LDIM) return;
    int row = idx / LDIM, l = idx % LDIM;
    float a0 = 0.f, a1 = 0.f, a2 = 0.f, a3 = 0.f;
    if (row < EDIM) {
        #pragma unroll 4
        for (int u = 0; u < UDIM; u += 4) {
            a0 += g_S[u * EDIM + row] * LE[u * LDIM + l];
            a1 += g_S[(u + 1) * EDIM + row] * LE[(u + 1) * LDIM + l];
            a2 += g_S[(u + 2) * EDIM + row] * LE[(u + 2) * LDIM + l];
            a3 += g_S[(u + 3) * EDIM + row] * LE[(u + 3) * LDIM + l];
        }
        g_P1[row * LDIM + l] = (a0 + a1) + (a2 + a3);
    } else if (row < 2 * EDIM) {
        int k = row - EDIM;
        #pragma unroll 4
        for (int u = 0; u < UDIM; u += 4) {
            a0 += W8[u * 2 * EDIM + EDIM + k] * LE[u * LDIM + l];
            a1 += W8[(u + 1) * 2 * EDIM + EDIM + k] * LE[(u + 1) * LDIM + l];
            a2 += W8[(u + 2) * 2 * EDIM + EDIM + k] * LE[(u + 2) * LDIM + l];
            a3 += W8[(u + 3) * 2 * EDIM + EDIM + k] * LE[(u + 3) * LDIM + l];
        }
        g_Q1b[k * LDIM + l] = (a0 + a1) + (a2 + a3);
    } else {
        #pragma unroll 4
        for (int u = 0; u < UDIM; u += 4) {
            a0 += g_w[u] * LE[u * LDIM + l];
            a1 += g_w[u + 1] * LE[(u + 1) * LDIM + l];
            a2 += g_w[u + 2] * LE[(u + 2) * LDIM + l];
            a3 += g_w[u + 3] * LE[(u + 3) * LDIM + l];
        }
        g_c[l] = (a0 + a1) + (a2 + a3);
    }
}

// ---------------- prepC: pack folded-P fragments ---------------------------
__global__ void k_prepC() {
    int idx = blockIdx.x * blockDim.x + threadIdx.x;
    if (idx >= NKSF * NLT * 32) return;
    int ks = idx / (NLT * 32), rem = idx % (NLT * 32);
    int nt = rem >> 5, l = rem & 31;
    int n = nt * 8 + (l >> 2);
    int c0 = (l & 3) * 2;
    uint32_t hreg[2], lreg[2];
    #pragma unroll
    for (int r = 0; r < 2; r++) {
        uint32_t hp = 0, lp = 0;
        #pragma unroll
        for (int h = 0; h < 2; h++) {
            int k = ks * 16 + r * 8 + c0 + h;
            float w = 0.f;
            if (k < EDIM) w = g_P1[k * LDIM + n];
            else if (k < 2 * EDIM) w = g_Q1b[(k - EDIM) * LDIM + n];
            __nv_bfloat16 hi = __float2bfloat16(w);
            __nv_bfloat16 lo = __float2bfloat16(w - __bfloat162float(hi));
            hp |= (uint32_t)__bfloat16_as_ushort(hi) << (h * 16);
            lp |= (uint32_t)__bfloat16_as_ushort(lo) << (h * 16);
        }
        hreg[r] = hp; lreg[r] = lp;
    }
    g_Pfh[idx] = make_uint2(hreg[0], hreg[1]);
    g_Pfl[idx] = make_uint2(lreg[0], lreg[1]);
}

// ---------------- attention pools -> q -------------------------------------
__global__ void __launch_bounds__(256) k_attn6(const float* __restrict__ x, int B) {
    __shared__ float zs[2][2][64];
    __shared__ float qp[2][4][2][EDIM];

    int tid = threadIdx.x;
    int g = tid >> 7, wg_tid = tid & 127;
    int lane = tid & 31;
    int w = tid >> 5;
    int ww = w & 3;
    int b = blockIdx.x * 2 + g;
    bool bv = (b < B);
    const float* xb = x + (size_t)b * NDIM * EDIM;

    float4 u0 = make_float4(0.f, 0.f, 0.f, 0.f), u1 = u0;
    if (lane < 25) {
        u0 = *(const float4*)&g_u[4 * lane];
        u1 = *(const float4*)&g_u[EDIM + 4 * lane];
    }
    float z00 = g_z0[0], z01 = g_z0[1];

    int nrows = (ww < 2) ? 13 : 12;
    float4 xv[13];
    #pragma unroll
    for (int r = 0; r < 13; r++) {
        xv[r] = make_float4(0.f, 0.f, 0.f, 0.f);
        if (r < nrows && bv && lane < 25) {
            int n = ww + r * 4;
            xv[r] = *(const float4*)&xb[n * EDIM + 4 * lane];
        }
    }

    #pragma unroll
    for (int r = 0; r < 13; r++) {
        if (r < nrows) {
            float y0 = xv[r].x * u0.x + xv[r].y * u0.y + xv[r].z * u0.z + xv[r].w * u0.w;
            float y1 = xv[r].x * u1.x + xv[r].y * u1.y + xv[r].z * u1.z + xv[r].w * u1.w;
            #pragma unroll
            for (int off = 16; off; off >>= 1) {
                y0 += __shfl_xor_sync(0xffffffffu, y0, off);
                y1 += __shfl_xor_sync(0xffffffffu, y1, off);
            }
            if (lane == 0) {
                int n = ww + r * 4;
                zs[g][0][n] = expf(y0 + z00);
                zs[g][1][n] = expf(y1 + z01);
            }
        }
    }
    __syncthreads();

    if (w < 4) {
        int gg = w >> 1, pool = w & 1;
        float z1 = zs[gg][pool][lane];
        float z2 = (lane < NDIM - 32) ? zs[gg][pool][32 + lane] : -1e30f;
        float m = fmaxf(z1, z2);
        #pragma unroll
        for (int off = 16; off; off >>= 1)
            m = fmaxf(m, __shfl_xor_sync(0xffffffffu, m, off));
        float e1 = expf(z1 - m);
        float e2 = (lane < NDIM - 32) ? expf(z2 - m) : 0.f;
        float s = e1 + e2;
        #pragma unroll
        for (int off = 16; off; off >>= 1)
            s += __shfl_xor_sync(0xffffffffu, s, off);
        zs[gg][pool][lane] = e1 / s;
        if (lane < NDIM - 32) zs[gg][pool][32 + lane] = e2 / s;
    }
    __syncthreads();

    float4 q0 = make_float4(0.f, 0.f, 0.f, 0.f), q1 = q0;
    #pragma unroll
    for (int r = 0; r < 13; r++) {
        if (r < nrows) {
            int n = ww + r * 4;
            float w0 = zs[g][0][n], w1 = zs[g][1][n];
            q0.x += w0 * xv[r].x; q0.y += w0 * xv[r].y;
            q0.z += w0 * xv[r].z; q0.w += w0 * xv[r].w;
            q1.x += w1 * xv[r].x; q1.y += w1 * xv[r].y;
            q1.z += w1 * xv[r].z; q1.w += w1 * xv[r].w;
        }
    }
    if (lane < 25) {
        *(float4*)&qp[g][ww][0][4 * lane] = q0;
        *(float4*)&qp[g][ww][1][4 * lane] = q1;
    }
    __syncthreads();

    if (bv) {
        for (int kk = wg_tid; kk < 2 * EDIM; kk += 128) {
            int pool = kk / EDIM, e = kk % EDIM;
            g_q[(size_t)b * 2 * EDIM + kk] =
                qp[g][0][pool][e] + qp[g][1][pool][e] +
                qp[g][2][pool][e] + qp[g][3][pool][e];
        }
    }
}

// ---------------- kernel H5 ------------------------------------------------
#define H5_SMEM_BYTES (TMC * KH * 4)

__global__ void __launch_bounds__(256) k_h5(const float* __restrict__ b5, int B) {
    extern __shared__ float As[];

    int tid = threadIdx.x;
    int b0  = blockIdx.x * TMC;

    for (int li = tid; li < TMC * KH; li += 256) {
        int r = li / KH, k = li % KH;
        int b = b0 + r;
        As[li] = (b < B && k < 2 * EDIM) ? g_q[(size_t)b * 2 * EDIM + k] : 0.f;
    }
    __syncthreads();

    int lane = tid & 31, warp = tid >> 5;
    int wm = warp >> 1, wn = warp & 1;
    int ar = wm * 16 + (lane >> 2);
    int ac = (lane & 3) * 2;

    uint32_t ah[NKH][4], al[NKH][4];
    #pragma unroll
    for (int ks = 0; ks < NKH; ks++) {
        float2 v00 = *(const float2*)&As[ar * KH + ks * 16 + ac];
        float2 v10 = *(const float2*)&As[(ar + 8) * KH + ks * 16 + ac];
        float2 v01 = *(const float2*)&As[ar * KH + ks * 16 + ac + 8];
        float2 v11 = *(const float2*)&As[(ar + 8) * KH + ks * 16 + ac + 8];
        splitpack(v00.x, v00.y, ah[ks][0], al[ks][0]);
        splitpack(v10.x, v10.y, ah[ks][1], al[ks][1]);
        splitpack(v01.x, v01.y, ah[ks][2], al[ks][2]);
        splitpack(v11.x, v11.y, ah[ks][3], al[ks][3]);
    }

    int colb = (lane & 3) * 2;
    for (int nt = wn; nt < NTH; nt += 2) {
        int col = nt * 8 + colb;
        float bb0 = (col < EDIM) ? b5[col] : 0.f;
        float bb1 = (col + 1 < EDIM) ? b5[col + 1] : 0.f;
        float acc4[4] = {bb0, bb1, bb0, bb1};
        #pragma unroll
        for (int ks = 0; ks < NKH; ks++) {
            uint2 Bh = g_W5fh[(ks * NTH + nt) * 32 + lane];
            uint2 Bl = g_W5fl[(ks * NTH + nt) * 32 + lane];
            mma16816(acc4, ah[ks], Bh);
            mma16816(acc4, ah[ks], Bl);
            mma16816(acc4, al[ks], Bh);
        }
        int bA = b0 + ar, bB = bA + 8;
        if (col < EDIM) {
            if (bA < B)
                *(float2*)&g_h5[(size_t)bA * EDIM + col] = make_float2(acc4[0], acc4[1]);
            if (bB < B)
                *(float2*)&g_h5[(size_t)bB * EDIM + col] = make_float2(acc4[2], acc4[3]);
        }
    }
}

// ---------------- kernel B -------------------------------------------------
#define SB_H5 0
#define SB_PR 51712
#define SB_BH 72192
#define SB_BL 104960
#define SB_SMEM 137728

__global__ void __launch_bounds__(512, 1) k_B(int B) {
    extern __shared__ __align__(16) char smem[];
    float* h5s = (float*)(smem + SB_H5);
    int2*  ps  = (int2*)(smem + SB_PR);

    int tid = threadIdx.x;
    int lane = tid & 31, warp = tid >> 5;
    int wm = warp >> 1, wn = warp & 1;
    int b0 = blockIdx.x * 128;
    int ks = blockIdx.y;

    for (int li = tid; li < 128 * EDIM; li += 512) {
        int r = li / EDIM, e = li % EDIM;
        int b = b0 + r;
        h5s[r * 101 + e] = (b < B) ? g_h5[(size_t)b * EDIM + e] : 0.f;
    }
    {
        const int4* src = (const int4*)(g_pairs + ks * KSLICE);
        int4* dst = (int4*)ps;
        for (int li = tid; li < KSLICE / 2; li += 512) dst[li] = src[li];
    }

    float acc[8][4];
    #pragma unroll
    for (int nt = 0; nt < 8; nt++)
        #pragma unroll
        for (int q = 0; q < 4; q++) acc[nt][q] = 0.f;

    auto stageB = [&](int ch) {
        int s = ch & 1;
        size_t goff = ((size_t)ks * NKS_SL + ch * 4) * 512;
        const float4* srcH = (const float4*)(g_Bfh + goff);
        const float4* srcL = (const float4*)(g_Bfl + goff);
        float4* dH = (float4*)(smem + SB_BH + s * 16384);
        float4* dL = (float4*)(smem + SB_BL + s * 16384);
        #pragma unroll
        for (int q = 0; q < 2; q++) {
            dH[tid + q * 512] = srcH[tid + q * 512];
            dL[tid + q * 512] = srcL[tid + q * 512];
        }
    };

    stageB(0);
    __syncthreads();

    int c0 = (lane & 3) * 2;
    int ar = wm * 16 + (lane >> 2);
    const float* ra = &h5s[ar * 101];
    const float* rb = &h5s[(ar + 8) * 101];

    for (int ch = 0; ch < NCHUNK; ch++) {
        if (ch + 1 < NCHUNK) stageB(ch + 1);
        int s = ch & 1;
        const uint2* bhB = (const uint2*)(smem + SB_BH + s * 16384);
        const uint2* blB = (const uint2*)(smem + SB_BL + s * 16384);
        #pragma unroll
        for (int kl = 0; kl < 4; kl++) {
            int kb = (ch * 4 + kl) * 16;
            int2 pA0 = ps[kb + c0], pA1 = ps[kb + c0 + 1];
            int2 pB0 = ps[kb + c0 + 8], pB1 = ps[kb + c0 + 9];
            uint32_t ahi[4], alo[4];
            mkfrag(ra, pA0, pA1, ahi[0], alo[0]);
            mkfrag(rb, pA0, pA1, ahi[1], alo[1]);
            mkfrag(ra, pB0, pB1, ahi[2], alo[2]);
            mkfrag(rb, pB0, pB1, ahi[3], alo[3]);
            const uint2* bh = bhB + kl * 512 + lane;
            const uint2* bl = blB + kl * 512 + lane;
            #pragma unroll
            for (int nt = 0; nt < 8; nt++) {
                uint2 Bh = bh[(wn * 8 + nt) * 32];
                uint2 Bl = bl[(wn * 8 + nt) * 32];
                mma16816(acc[nt], ahi, Bh);
                mma16816(acc[nt], ahi, Bl);
                mma16816(acc[nt], alo, Bh);
            }
        }
        __syncthreads();
    }

    float* base = g_h7p + (size_t)ks * MAXB * NP;
    int bA = b0 + ar, bB = bA + 8;
    #pragma unroll
    for (int nt = 0; nt < 8; nt++) {
        int col = wn * 64 + nt * 8 + (lane & 3) * 2;
        if (bA < B)
            *(float2*)&base[(size_t)bA * NP + col] = make_float2(acc[nt][0], acc[nt][1]);
        if (bB < B)
            *(float2*)&base[(size_t)bB * NP + col] = make_float2(acc[nt][2], acc[nt][3]);
    }
}

// ---------------- kernel C2 ------------------------------------------------
#define C2_SMEM_BYTES (TMC * KF * 4)

__global__ void __launch_bounds__(256) k_C2(float* __restrict__ out, int B) {
    extern __shared__ float As[];

    int tid = threadIdx.x;
    int b0  = blockIdx.x * TMC;
    int nh  = blockIdx.y;

    for (int li = tid; li < TMC * KF; li += 256) {
        int r = li / KF, k = li % KF;
        int b = b0 + r;
        float val = 0.f;
        if (b < B) {
            if (k < EDIM) {
                val = g_h5[(size_t)b * EDIM + k];
            } else if (k < 2 * EDIM) {
                int e = k - EDIM;
                val = g_h7p[(size_t)b * NP + e] +
                      g_h7p[((size_t)MAXB + b) * NP + e];
            }
        }
        As[li] = val;
    }
    __syncthreads();

    int lane = tid & 31, warp = tid >> 5;
    int wm = warp >> 1, wn = warp & 1;
    int ar = wm * 16 + (lane >> 2);
    int ac = (lane & 3) * 2;

    uint32_t ah[NKSF][4], al[NKSF][4];
    #pragma unroll
    for (int ks = 0; ks < NKSF; ks++) {
        float2 v00 = *(const float2*)&As[ar * KF + ks * 16 + ac];
        float2 v10 = *(const float2*)&As[(ar + 8) * KF + ks * 16 + ac];
        float2 v01 = *(const float2*)&As[ar * KF + ks * 16 + ac + 8];
        float2 v11 = *(const float2*)&As[(ar + 8) * KF + ks * 16 + ac + 8];
        splitpack(v00.x, v00.y, ah[ks][0], al[ks][0]);
        splitpack(v10.x, v10.y, ah[ks][1], al[ks][1]);
        splitpack(v01.x, v01.y, ah[ks][2], al[ks][2]);
        splitpack(v11.x, v11.y, ah[ks][3], al[ks][3]);
    }

    int colb = (lane & 3) * 2;
    for (int nt = wn + 2 * nh; nt < NLT; nt += 4) {
        int col = nt * 8 + colb;
        float2 cv = *(const float2*)&g_c[col];
        float acc4[4] = {cv.x, cv.y, cv.x, cv.y};
        #pragma unroll
        for (int ks = 0; ks < NKSF; ks++) {
            uint2 Bh = g_Pfh[(ks * NLT + nt) * 32 + lane];
            uint2 Bl = g_Pfl[(ks * NLT + nt) * 32 + lane];
            mma16816(acc4, ah[ks], Bh);
            mma16816(acc4, ah[ks], Bl);
            mma16816(acc4, al[ks], Bh);
        }
        int bA = b0 + ar, bB = bA + 8;
        if (bA < B)
            *(float2*)&out[(size_t)bA * LDIM + col] = make_float2(acc4[0], acc4[1]);
        if (bB < B)
            *(float2*)&out[(size_t)bB * LDIM + col] = make_float2(acc4[2], acc4[3]);
    }
}

// ---------------- launch ----------------
extern "C" void kernel_launch(void* const* d_in, const int* in_sizes, int n_in,
                              void* d_out, int out_size) {
    const float* x  = (const float*)d_in[0];
    const float* v  = (const float*)d_in[1];
    const float* W1 = (const float*)d_in[2];
    const float* b1 = (const float*)d_in[3];
    const float* W2 = (const float*)d_in[4];
    const float* W3 = (const float*)d_in[5];
    const float* b3 = (const float*)d_in[6];
    const float* W4 = (const float*)d_in[7];
    const float* W5 = (const float*)d_in[8];
    const float* b5 = (const float*)d_in[9];
    const float* W6 = (const float*)d_in[10];
    const float* b6 = (const float*)d_in[11];
    const float* W7 = (const float*)d_in[12];
    const float* b7 = (const float*)d_in[13];
    const float* W8 = (const float*)d_in[14];
    const float* b8 = (const float*)d_in[15];
    const float* LE = (const float*)d_in[16];
    float* out = (float*)d_out;

    int B = in_sizes[0] / (NDIM * EDIM);

    k_pairs<<<(KPAD + 255) / 256, 256>>>();
    k_prep1<<<(P1_W5 + 255) / 256, 256>>>(v, W7, W5, W1, b1, W2, W3, b3, W4,
                                          W6, W8, b6, b7, b8);
    k_prepB<<<((2 * EDIM + 1) * LDIM + 255) / 256, 256>>>(W8, LE);
    k_prepC<<<(NKSF * NLT * 32 + 255) / 256, 256>>>();

    k_attn6<<<(B + 1) / 2, 256>>>(x, B);

    cudaFuncSetAttribute(k_h5, cudaFuncAttributeMaxDynamicSharedMemorySize, H5_SMEM_BYTES);
    k_h5<<<(B + TMC - 1) / TMC, 256, H5_SMEM_BYTES>>>(b5, B);

    cudaFuncSetAttribute(k_B, cudaFuncAttributeMaxDynamicSharedMemorySize, SB_SMEM);
    dim3 bgrid((B + 127) / 128, KSPLIT);
    k_B<<<bgrid, 512, SB_SMEM>>>(B);

    cudaFuncSetAttribute(k_C2, cudaFuncAttributeMaxDynamicSharedMemorySize, C2_SMEM_BYTES);
    dim3 cgrid((B + TMC - 1) / TMC, 2);
    k_C2<<<cgrid, 256, C2_SMEM_BYTES>>>(out, B);
}

// round 17
// speedup vs baseline: 1.6434x; 1.6434x over previous
#include <cuda_runtime.h>
#include <cuda_bf16.h>
#include <cstdint>

#define EDIM 100
#define NDIM 50
#define TDIM 8
#define CDIM 4
#define UDIM 100
#define LDIM 1000
#define NPAIR 4950
#define KPAD  5120
#define NP    128
#define KSPLIT 2
#define KSLICE (KPAD / KSPLIT)        // 2560
#define NKSTEP (KPAD / 16)            // 320
#define NKS_SL (KSLICE / 16)          // 160
#define NCHUNK (NKS_SL / 4)           // 40
#define MAXB  8192
#define TMC   64
#define KF    208
#define NKSF  13
#define NLT   125
#define KH    208
#define NKH   13
#define NTH   13

// ---------------- device scratch ----------------
__device__ __align__(16) int2  g_pairs[KPAD];
__device__ float g_q[MAXB * 2 * EDIM];
__device__ float g_h5[MAXB * EDIM];
__device__ float g_h7p[KSPLIT * MAXB * NP];
__device__ __align__(16) float g_u[2 * EDIM];
__device__ float g_z0[2];
__device__ float g_Q1[2 * EDIM * LDIM];
__device__ float g_P1[EDIM * LDIM];
__device__ float g_c[LDIM];
__device__ __align__(16) uint2 g_Bfh[NKSTEP * 16 * 32];
__device__ __align__(16) uint2 g_Bfl[NKSTEP * 16 * 32];
__device__ __align__(16) uint2 g_Pfh[NKSF * NLT * 32];
__device__ __align__(16) uint2 g_Pfl[NKSF * NLT * 32];
__device__ __align__(16) uint2 g_W5fh[NKH * NTH * 32];
__device__ __align__(16) uint2 g_W5fl[NKH * NTH * 32];

// ---------------- helpers ----------------
__device__ __forceinline__ void mma16816(float* d, const uint32_t* a, uint2 b) {
    asm volatile(
        "mma.sync.aligned.m16n8k16.row.col.f32.bf16.bf16.f32 "
        "{%0,%1,%2,%3}, {%4,%5,%6,%7}, {%8,%9}, {%0,%1,%2,%3};"
        : "+f"(d[0]), "+f"(d[1]), "+f"(d[2]), "+f"(d[3])
        : "r"(a[0]), "r"(a[1]), "r"(a[2]), "r"(a[3]), "r"(b.x), "r"(b.y));
}
__device__ __forceinline__ void mkfrag(const float* rw, int2 p0, int2 p1,
                                       uint32_t& hi, uint32_t& lo) {
    float v0 = rw[p0.x] * rw[p0.y];
    float v1 = rw[p1.x] * rw[p1.y];
    __nv_bfloat16 h0 = __float2bfloat16(v0), h1 = __float2bfloat16(v1);
    __nv_bfloat16 l0 = __float2bfloat16(v0 - __bfloat162float(h0));
    __nv_bfloat16 l1 = __float2bfloat16(v1 - __bfloat162float(h1));
    hi = (uint32_t)__bfloat16_as_ushort(h0) | ((uint32_t)__bfloat16_as_ushort(h1) << 16);
    lo = (uint32_t)__bfloat16_as_ushort(l0) | ((uint32_t)__bfloat16_as_ushort(l1) << 16);
}
__device__ __forceinline__ void splitpack(float v0, float v1,
                                          uint32_t& hi, uint32_t& lo) {
    __nv_bfloat16 h0 = __float2bfloat16(v0), h1 = __float2bfloat16(v1);
    __nv_bfloat16 l0 = __float2bfloat16(v0 - __bfloat162float(h0));
    __nv_bfloat16 l1 = __float2bfloat16(v1 - __bfloat162float(h1));
    hi = (uint32_t)__bfloat16_as_ushort(h0) | ((uint32_t)__bfloat16_as_ushort(h1) << 16);
    lo = (uint32_t)__bfloat16_as_ushort(l0) | ((uint32_t)__bfloat16_as_ushort(l1) << 16);
}

// ---------------- pair table ----------------
__global__ void k_pairs() {
    int p = blockIdx.x * blockDim.x + threadIdx.x;
    if (p >= KPAD) return;
    int i = 0, j = 0;
    if (p < NPAIR) {
        int rem = p;
        while (rem >= EDIM - 1 - i) { rem -= EDIM - 1 - i; i++; }
        j = i + 1 + rem;
    }
    g_pairs[p] = make_int2(i, j);
}

// ---------------- build W7 B-fragments ----------------
__global__ void k_bfrag(const float* __restrict__ v, const float* __restrict__ W7) {
    int idx = blockIdx.x * blockDim.x + threadIdx.x;
    if (idx >= NKSTEP * 512) return;
    int ks = idx >> 9, rem = idx & 511;
    int nt = rem >> 5, l = rem & 31;
    int n = nt * 8 + (l >> 2);
    int c0 = (l & 3) * 2;
    uint32_t hreg[2], lreg[2];
    #pragma unroll
    for (int r = 0; r < 2; r++) {
        uint32_t hp = 0, lp = 0;
        #pragma unroll
        for (int h = 0; h < 2; h++) {
            int k = ks * 16 + r * 8 + c0 + h;
            float w = 0.f;
            if (k < NPAIR && n < EDIM) {
                int2 ij = g_pairs[k];
                float vv = 0.f;
                #pragma unroll
                for (int cc = 0; cc < CDIM; cc++)
                    vv += v[ij.x * CDIM + cc] * v[ij.y * CDIM + cc];
                w = W7[n * NPAIR + k] * vv;
            }
            __nv_bfloat16 hi = __float2bfloat16(w);
            __nv_bfloat16 lo = __float2bfloat16(w - __bfloat162float(hi));
            hp |= (uint32_t)__bfloat16_as_ushort(hi) << (h * 16);
            lp |= (uint32_t)__bfloat16_as_ushort(lo) << (h * 16);
        }
        hreg[r] = hp; lreg[r] = lp;
    }
    g_Bfh[idx] = make_uint2(hreg[0], hreg[1]);
    g_Bfl[idx] = make_uint2(lreg[0], lreg[1]);
}

// ---------------- build W5 B-fragments -------------------------------------
__global__ void k_w5f(const float* __restrict__ W5) {
    int idx = blockIdx.x * blockDim.x + threadIdx.x;
    if (idx >= NKH * NTH * 32) return;
    int ks = idx / (NTH * 32), rem = idx % (NTH * 32);
    int nt = rem >> 5, l = rem & 31;
    int n = nt * 8 + (l >> 2);
    int c0 = (l & 3) * 2;
    uint32_t hreg[2], lreg[2];
    #pragma unroll
    for (int r = 0; r < 2; r++) {
        uint32_t hp = 0, lp = 0;
        #pragma unroll
        for (int h = 0; h < 2; h++) {
            int k = ks * 16 + r * 8 + c0 + h;
            float w = (k < 2 * EDIM && n < EDIM) ? W5[n * 2 * EDIM + k] : 0.f;
            __nv_bfloat16 hi = __float2bfloat16(w);
            __nv_bfloat16 lo = __float2bfloat16(w - __bfloat162float(hi));
            hp |= (uint32_t)__bfloat16_as_ushort(hi) << (h * 16);
            lp |= (uint32_t)__bfloat16_as_ushort(lo) << (h * 16);
        }
        hreg[r] = hp; lreg[r] = lp;
    }
    g_W5fh[idx] = make_uint2(hreg[0], hreg[1]);
    g_W5fl[idx] = make_uint2(lreg[0], lreg[1]);
}

// ---------------- fold: Q1 = W8^T @ LE  (scalar, high thread count) --------
__global__ void k_q1(const float* __restrict__ W8, const float* __restrict__ LE) {
    int idx = blockIdx.x * blockDim.x + threadIdx.x;
    if (idx >= 2 * EDIM * LDIM) return;
    int k = idx / LDIM, l = idx % LDIM;
    float a0 = 0.f, a1 = 0.f;
    #pragma unroll 2
    for (int u = 0; u < UDIM; u += 2) {
        a0 += W8[u * 2 * EDIM + k] * LE[u * LDIM + l];
        a1 += W8[(u + 1) * 2 * EDIM + k] * LE[(u + 1) * LDIM + l];
    }
    g_Q1[idx] = a0 + a1;
}

// ---------------- fold: P1 = W6^T @ Q1a ; c  (scalar) ----------------------
__global__ void k_p1c(const float* __restrict__ W6, const float* __restrict__ b6,
                      const float* __restrict__ b7, const float* __restrict__ b8,
                      const float* __restrict__ LE) {
    int idx = blockIdx.x * blockDim.x + threadIdx.x;
    if (idx < EDIM * LDIM) {
        int e = idx / LDIM, l = idx % LDIM;
        float a0 = 0.f, a1 = 0.f;
        #pragma unroll 2
        for (int k = 0; k < EDIM; k += 2) {
            a0 += W6[k * EDIM + e] * g_Q1[k * LDIM + l];
            a1 += W6[(k + 1) * EDIM + e] * g_Q1[(k + 1) * LDIM + l];
        }
        g_P1[idx] = a0 + a1;
    } else if (idx < EDIM * LDIM + LDIM) {
        int l = idx - EDIM * LDIM;
        float a = 0.f;
        #pragma unroll 2
        for (int k = 0; k < EDIM; k++) {
            a += b6[k] * g_Q1[k * LDIM + l];
            a += b7[k] * g_Q1[(EDIM + k) * LDIM + l];
            a += b8[k] * LE[k * LDIM + l];
        }
        g_c[l] = a;
    }
}

// ---------------- build folded-P fragments ---------------------------------
__global__ void k_pf() {
    int idx = blockIdx.x * blockDim.x + threadIdx.x;
    if (idx >= NKSF * NLT * 32) return;
    int ks = idx / (NLT * 32), rem = idx % (NLT * 32);
    int nt = rem >> 5, l = rem & 31;
    int n = nt * 8 + (l >> 2);
    int c0 = (l & 3) * 2;
    uint32_t hreg[2], lreg[2];
    #pragma unroll
    for (int r = 0; r < 2; r++) {
        uint32_t hp = 0, lp = 0;
        #pragma unroll
        for (int h = 0; h < 2; h++) {
            int k = ks * 16 + r * 8 + c0 + h;
            float w = 0.f;
            if (k < EDIM) w = g_P1[k * LDIM + n];
            else if (k < 2 * EDIM) w = g_Q1[k * LDIM + n];
            __nv_bfloat16 hi = __float2bfloat16(w);
            __nv_bfloat16 lo = __float2bfloat16(w - __bfloat162float(hi));
            hp |= (uint32_t)__bfloat16_as_ushort(hi) << (h * 16);
            lp |= (uint32_t)__bfloat16_as_ushort(lo) << (h * 16);
        }
        hreg[r] = hp; lreg[r] = lp;
    }
    g_Pfh[idx] = make_uint2(hreg[0], hreg[1]);
    g_Pfl[idx] = make_uint2(lreg[0], lreg[1]);
}

// ---------------- prep: fold attn MLP --------------------------------------
__global__ void k_prep(const float* __restrict__ W1, const float* __restrict__ b1,
                       const float* __restrict__ W2,
                       const float* __restrict__ W3, const float* __restrict__ b3,
                       const float* __restrict__ W4) {
    int idx = blockIdx.x * blockDim.x + threadIdx.x;
    if (idx < 2 * EDIM) {
        int pool = idx / EDIM, e = idx % EDIM;
        const float* Wa = pool ? W3 : W1;
        const float* Wb = pool ? W4 : W2;
        float u = 0.f;
        #pragma unroll
        for (int t = 0; t < TDIM; t++) u += Wb[t] * Wa[t * EDIM + e];
        g_u[idx] = u;
    } else if (idx < 2 * EDIM + 2) {
        int pool = idx - 2 * EDIM;
        const float* ba = pool ? b3 : b1;
        const float* Wb = pool ? W4 : W2;
        float z = 0.f;
        #pragma unroll
        for (int t = 0; t < TDIM; t++) z += Wb[t] * ba[t];
        g_z0[pool] = z;
    }
}

// ---------------- attention pools -> q -------------------------------------
__global__ void __launch_bounds__(256) k_attn6(const float* __restrict__ x, int B) {
    __shared__ float zs[2][2][64];
    __shared__ float qp[2][4][2][EDIM];

    int tid = threadIdx.x;
    int g = tid >> 7, wg_tid = tid & 127;
    int lane = tid & 31;
    int w = tid >> 5;
    int ww = w & 3;
    int b = blockIdx.x * 2 + g;
    bool bv = (b < B);
    const float* xb = x + (size_t)b * NDIM * EDIM;

    float4 u0 = make_float4(0.f, 0.f, 0.f, 0.f), u1 = u0;
    if (lane < 25) {
        u0 = *(const float4*)&g_u[4 * lane];
        u1 = *(const float4*)&g_u[EDIM + 4 * lane];
    }
    float z00 = g_z0[0], z01 = g_z0[1];

    int nrows = (ww < 2) ? 13 : 12;
    float4 xv[13];
    #pragma unroll
    for (int r = 0; r < 13; r++) {
        xv[r] = make_float4(0.f, 0.f, 0.f, 0.f);
        if (r < nrows && bv && lane < 25) {
            int n = ww + r * 4;
            xv[r] = *(const float4*)&xb[n * EDIM + 4 * lane];
        }
    }

    #pragma unroll
    for (int r = 0; r < 13; r++) {
        if (r < nrows) {
            float y0 = xv[r].x * u0.x + xv[r].y * u0.y + xv[r].z * u0.z + xv[r].w * u0.w;
            float y1 = xv[r].x * u1.x + xv[r].y * u1.y + xv[r].z * u1.z + xv[r].w * u1.w;
            #pragma unroll
            for (int off = 16; off; off >>= 1) {
                y0 += __shfl_xor_sync(0xffffffffu, y0, off);
                y1 += __shfl_xor_sync(0xffffffffu, y1, off);
            }
            if (lane == 0) {
                int n = ww + r * 4;
                zs[g][0][n] = expf(y0 + z00);
                zs[g][1][n] = expf(y1 + z01);
            }
        }
    }
    __syncthreads();

    if (w < 4) {
        int gg = w >> 1, pool = w & 1;
        float z1 = zs[gg][pool][lane];
        float z2 = (lane < NDIM - 32) ? zs[gg][pool][32 + lane] : -1e30f;
        float m = fmaxf(z1, z2);
        #pragma unroll
        for (int off = 16; off; off >>= 1)
            m = fmaxf(m, __shfl_xor_sync(0xffffffffu, m, off));
        float e1 = expf(z1 - m);
        float e2 = (lane < NDIM - 32) ? expf(z2 - m) : 0.f;
        float s = e1 + e2;
        #pragma unroll
        for (int off = 16; off; off >>= 1)
            s += __shfl_xor_sync(0xffffffffu, s, off);
        zs[gg][pool][lane] = e1 / s;
        if (lane < NDIM - 32) zs[gg][pool][32 + lane] = e2 / s;
    }
    __syncthreads();

    float4 q0 = make_float4(0.f, 0.f, 0.f, 0.f), q1 = q0;
    #pragma unroll
    for (int r = 0; r < 13; r++) {
        if (r < nrows) {
            int n = ww + r * 4;
            float w0 = zs[g][0][n], w1 = zs[g][1][n];
            q0.x += w0 * xv[r].x; q0.y += w0 * xv[r].y;
            q0.z += w0 * xv[r].z; q0.w += w0 * xv[r].w;
            q1.x += w1 * xv[r].x; q1.y += w1 * xv[r].y;
            q1.z += w1 * xv[r].z; q1.w += w1 * xv[r].w;
        }
    }
    if (lane < 25) {
        *(float4*)&qp[g][ww][0][4 * lane] = q0;
        *(float4*)&qp[g][ww][1][4 * lane] = q1;
    }
    __syncthreads();

    if (bv) {
        for (int kk = wg_tid; kk < 2 * EDIM; kk += 128) {
            int pool = kk / EDIM, e = kk % EDIM;
            g_q[(size_t)b * 2 * EDIM + kk] =
                qp[g][0][pool][e] + qp[g][1][pool][e] +
                qp[g][2][pool][e] + qp[g][3][pool][e];
        }
    }
}

// ---------------- kernel H5: h5 = q @ W5^T + b5 ----------------------------
#define H5_SMEM_BYTES (TMC * KH * 4)

__global__ void __launch_bounds__(256) k_h5(const float* __restrict__ b5, int B) {
    extern __shared__ float As[];

    int tid = threadIdx.x;
    int b0  = blockIdx.x * TMC;

    for (int li = tid; li < TMC * KH; li += 256) {
        int r = li / KH, k = li % KH;
        int b = b0 + r;
        As[li] = (b < B && k < 2 * EDIM) ? g_q[(size_t)b * 2 * EDIM + k] : 0.f;
    }
    __syncthreads();

    int lane = tid & 31, warp = tid >> 5;
    int wm = warp >> 1, wn = warp & 1;
    int ar = wm * 16 + (lane >> 2);
    int ac = (lane & 3) * 2;

    uint32_t ah[NKH][4], al[NKH][4];
    #pragma unroll
    for (int ks = 0; ks < NKH; ks++) {
        float2 v00 = *(const float2*)&As[ar * KH + ks * 16 + ac];
        float2 v10 = *(const float2*)&As[(ar + 8) * KH + ks * 16 + ac];
        float2 v01 = *(const float2*)&As[ar * KH + ks * 16 + ac + 8];
        float2 v11 = *(const float2*)&As[(ar + 8) * KH + ks * 16 + ac + 8];
        splitpack(v00.x, v00.y, ah[ks][0], al[ks][0]);
        splitpack(v10.x, v10.y, ah[ks][1], al[ks][1]);
        splitpack(v01.x, v01.y, ah[ks][2], al[ks][2]);
        splitpack(v11.x, v11.y, ah[ks][3], al[ks][3]);
    }

    int colb = (lane & 3) * 2;
    for (int nt = wn; nt < NTH; nt += 2) {
        int col = nt * 8 + colb;
        float bb0 = (col < EDIM) ? b5[col] : 0.f;
        float bb1 = (col + 1 < EDIM) ? b5[col + 1] : 0.f;
        float acc4[4] = {bb0, bb1, bb0, bb1};
        #pragma unroll
        for (int ks = 0; ks < NKH; ks++) {
            uint2 Bh = g_W5fh[(ks * NTH + nt) * 32 + lane];
            uint2 Bl = g_W5fl[(ks * NTH + nt) * 32 + lane];
            mma16816(acc4, ah[ks], Bh);
            mma16816(acc4, ah[ks], Bl);
            mma16816(acc4, al[ks], Bh);
        }
        int bA = b0 + ar, bB = bA + 8;
        if (col < EDIM) {
            if (bA < B)
                *(float2*)&g_h5[(size_t)bA * EDIM + col] = make_float2(acc4[0], acc4[1]);
            if (bB < B)
                *(float2*)&g_h5[(size_t)bB * EDIM + col] = make_float2(acc4[2], acc4[3]);
        }
    }
}

// ---------------- kernel B: split-bf16 mma, 512 threads --------------------
#define SB_H5 0
#define SB_PR 51712
#define SB_BH 72192
#define SB_BL 104960
#define SB_SMEM 137728

__global__ void __launch_bounds__(512, 1) k_B(int B) {
    extern __shared__ __align__(16) char smem[];
    float* h5s = (float*)(smem + SB_H5);
    int2*  ps  = (int2*)(smem + SB_PR);

    int tid = threadIdx.x;
    int lane = tid & 31, warp = tid >> 5;
    int wm = warp >> 1, wn = warp & 1;
    int b0 = blockIdx.x * 128;
    int ks = blockIdx.y;

    for (int li = tid; li < 128 * EDIM; li += 512) {
        int r = li / EDIM, e = li % EDIM;
        int b = b0 + r;
        h5s[r * 101 + e] = (b < B) ? g_h5[(size_t)b * EDIM + e] : 0.f;
    }
    {
        const int4* src = (const int4*)(g_pairs + ks * KSLICE);
        int4* dst = (int4*)ps;
        for (int li = tid; li < KSLICE / 2; li += 512) dst[li] = src[li];
    }

    float acc[8][4];
    #pragma unroll
    for (int nt = 0; nt < 8; nt++)
        #pragma unroll
        for (int q = 0; q < 4; q++) acc[nt][q] = 0.f;

    auto stageB = [&](int ch) {
        int s = ch & 1;
        size_t goff = ((size_t)ks * NKS_SL + ch * 4) * 512;
        const float4* srcH = (const float4*)(g_Bfh + goff);
        const float4* srcL = (const float4*)(g_Bfl + goff);
        float4* dH = (float4*)(smem + SB_BH + s * 16384);
        float4* dL = (float4*)(smem + SB_BL + s * 16384);
        #pragma unroll
        for (int q = 0; q < 2; q++) {
            dH[tid + q * 512] = srcH[tid + q * 512];
            dL[tid + q * 512] = srcL[tid + q * 512];
        }
    };

    stageB(0);
    __syncthreads();

    int c0 = (lane & 3) * 2;
    int ar = wm * 16 + (lane >> 2);
    const float* ra = &h5s[ar * 101];
    const float* rb = &h5s[(ar + 8) * 101];

    for (int ch = 0; ch < NCHUNK; ch++) {
        if (ch + 1 < NCHUNK) stageB(ch + 1);
        int s = ch & 1;
        const uint2* bhB = (const uint2*)(smem + SB_BH + s * 16384);
        const uint2* blB = (const uint2*)(smem + SB_BL + s * 16384);
        #pragma unroll
        for (int kl = 0; kl < 4; kl++) {
            int kb = (ch * 4 + kl) * 16;
            int2 pA0 = ps[kb + c0], pA1 = ps[kb + c0 + 1];
            int2 pB0 = ps[kb + c0 + 8], pB1 = ps[kb + c0 + 9];
            uint32_t ahi[4], alo[4];
            mkfrag(ra, pA0, pA1, ahi[0], alo[0]);
            mkfrag(rb, pA0, pA1, ahi[1], alo[1]);
            mkfrag(ra, pB0, pB1, ahi[2], alo[2]);
            mkfrag(rb, pB0, pB1, ahi[3], alo[3]);
            const uint2* bh = bhB + kl * 512 + lane;
            const uint2* bl = blB + kl * 512 + lane;
            #pragma unroll
            for (int nt = 0; nt < 8; nt++) {
                uint2 Bh = bh[(wn * 8 + nt) * 32];
                uint2 Bl = bl[(wn * 8 + nt) * 32];
                mma16816(acc[nt], ahi, Bh);
                mma16816(acc[nt], ahi, Bl);
                mma16816(acc[nt], alo, Bh);
            }
        }
        __syncthreads();
    }

    float* base = g_h7p + (size_t)ks * MAXB * NP;
    int bA = b0 + ar, bB = bA + 8;
    #pragma unroll
    for (int nt = 0; nt < 8; nt++) {
        int col = wn * 64 + nt * 8 + (lane & 3) * 2;
        if (bA < B)
            *(float2*)&base[(size_t)bA * NP + col] = make_float2(acc[nt][0], acc[nt][1]);
        if (bB < B)
            *(float2*)&base[(size_t)bB * NP + col] = make_float2(acc[nt][2], acc[nt][3]);
    }
}

// ---------------- kernel C2 ------------------------------------------------
#define C2_SMEM_BYTES (TMC * KF * 4)

__global__ void __launch_bounds__(256) k_C2(float* __restrict__ out, int B) {
    extern __shared__ float As[];

    int tid = threadIdx.x;
    int b0  = blockIdx.x * TMC;
    int nh  = blockIdx.y;

    for (int li = tid; li < TMC * KF; li += 256) {
        int r = li / KF, k = li % KF;
        int b = b0 + r;
        float val = 0.f;
        if (b < B) {
            if (k < EDIM) {
                val = g_h5[(size_t)b * EDIM + k];
            } else if (k < 2 * EDIM) {
                int e = k - EDIM;
                val = g_h7p[(size_t)b * NP + e] +
                      g_h7p[((size_t)MAXB + b) * NP + e];
            }
        }
        As[li] = val;
    }
    __syncthreads();

    int lane = tid & 31, warp = tid >> 5;
    int wm = warp >> 1, wn = warp & 1;
    int ar = wm * 16 + (lane >> 2);
    int ac = (lane & 3) * 2;

    uint32_t ah[NKSF][4], al[NKSF][4];
    #pragma unroll
    for (int ks = 0; ks < NKSF; ks++) {
        float2 v00 = *(const float2*)&As[ar * KF + ks * 16 + ac];
        float2 v10 = *(const float2*)&As[(ar + 8) * KF + ks * 16 + ac];
        float2 v01 = *(const float2*)&As[ar * KF + ks * 16 + ac + 8];
        float2 v11 = *(const float2*)&As[(ar + 8) * KF + ks * 16 + ac + 8];
        splitpack(v00.x, v00.y, ah[ks][0], al[ks][0]);
        splitpack(v10.x, v10.y, ah[ks][1], al[ks][1]);
        splitpack(v01.x, v01.y, ah[ks][2], al[ks][2]);
        splitpack(v11.x, v11.y, ah[ks][3], al[ks][3]);
    }

    int colb = (lane & 3) * 2;
    for (int nt = wn + 2 * nh; nt < NLT; nt += 4) {
        int col = nt * 8 + colb;
        float2 cv = *(const float2*)&g_c[col];
        float acc4[4] = {cv.x, cv.y, cv.x, cv.y};
        #pragma unroll
        for (int ks = 0; ks < NKSF; ks++) {
            uint2 Bh = g_Pfh[(ks * NLT + nt) * 32 + lane];
            uint2 Bl = g_Pfl[(ks * NLT + nt) * 32 + lane];
            mma16816(acc4, ah[ks], Bh);
            mma16816(acc4, ah[ks], Bl);
            mma16816(acc4, al[ks], Bh);
        }
        int bA = b0 + ar, bB = bA + 8;
        if (bA < B)
            *(float2*)&out[(size_t)bA * LDIM + col] = make_float2(acc4[0], acc4[1]);
        if (bB < B)
            *(float2*)&out[(size_t)bB * LDIM + col] = make_float2(acc4[2], acc4[3]);
    }
}

// ---------------- launch (two-stream overlap: prep chain || attn) ----------
extern "C" void kernel_launch(void* const* d_in, const int* in_sizes, int n_in,
                              void* d_out, int out_size) {
    const float* x  = (const float*)d_in[0];
    const float* v  = (const float*)d_in[1];
    const float* W1 = (const float*)d_in[2];
    const float* b1 = (const float*)d_in[3];
    const float* W2 = (const float*)d_in[4];
    const float* W3 = (const float*)d_in[5];
    const float* b3 = (const float*)d_in[6];
    const float* W4 = (const float*)d_in[7];
    const float* W5 = (const float*)d_in[8];
    const float* b5 = (const float*)d_in[9];
    const float* W6 = (const float*)d_in[10];
    const float* b6 = (const float*)d_in[11];
    const float* W7 = (const float*)d_in[12];
    const float* b7 = (const float*)d_in[13];
    const float* W8 = (const float*)d_in[14];
    const float* b8 = (const float*)d_in[15];
    const float* LE = (const float*)d_in[16];
    float* out = (float*)d_out;

    int B = in_sizes[0] / (NDIM * EDIM);

    // one-time host resources (created on first — uncaptured — call)
    static cudaStream_t s2 = nullptr;
    static cudaEvent_t evF = nullptr, evJ = nullptr;
    if (s2 == nullptr) {
        cudaStreamCreate(&s2);
        cudaEventCreateWithFlags(&evF, cudaEventDisableTiming);
        cudaEventCreateWithFlags(&evJ, cudaEventDisableTiming);
    }

    // main stream: tiny attn fold, then fork
    k_prep<<<(2 * EDIM + 2 + 255) / 256, 256>>>(W1, b1, W2, W3, b3, W4);
    cudaEventRecord(evF, 0);
    cudaStreamWaitEvent(s2, evF, 0);

    // side stream: full B-independent prep chain
    k_pairs<<<(KPAD + 255) / 256, 256, 0, s2>>>();
    k_bfrag<<<(NKSTEP * 512 + 255) / 256, 256, 0, s2>>>(v, W7);
    k_w5f<<<(NKH * NTH * 32 + 255) / 256, 256, 0, s2>>>(W5);
    k_q1<<<(2 * EDIM * LDIM + 255) / 256, 256, 0, s2>>>(W8, LE);
    k_p1c<<<(EDIM * LDIM + LDIM + 255) / 256, 256, 0, s2>>>(W6, b6, b7, b8, LE);
    k_pf<<<(NKSF * NLT * 32 + 255) / 256, 256, 0, s2>>>();
    cudaEventRecord(evJ, s2);

    // main stream: attention runs concurrently with prep chain
    k_attn6<<<(B + 1) / 2, 256>>>(x, B);

    // join, then the mma pipeline
    cudaStreamWaitEvent(0, evJ, 0);

    cudaFuncSetAttribute(k_h5, cudaFuncAttributeMaxDynamicSharedMemorySize, H5_SMEM_BYTES);
    k_h5<<<(B + TMC - 1) / TMC, 256, H5_SMEM_BYTES>>>(b5, B);

    cudaFuncSetAttribute(k_B, cudaFuncAttributeMaxDynamicSharedMemorySize, SB_SMEM);
    dim3 bgrid((B + 127) / 128, KSPLIT);
    k_B<<<bgrid, 512, SB_SMEM>>>(B);

    cudaFuncSetAttribute(k_C2, cudaFuncAttributeMaxDynamicSharedMemorySize, C2_SMEM_BYTES);
    dim3 cgrid((B + TMC - 1) / TMC, 2);
    k_C2<<<cgrid, 256, C2_SMEM_BYTES>>>(out, B);
}